// round 6
// baseline (speedup 1.0000x reference)
#include <cuda_runtime.h>
#include <cstdint>

// VectorQuantizer: F=32, N=4096, D=64, K=512
// out[f,n,:] = w[f,:,k*],  k* = argmin_k ||x - w_k||^2
// loss = 1.25 * mean((quantized - inputs)^2), appended at d_out[F*N*D]
//
// R5: TILE_R=64 (8 rows/lane), single barrier/tile via ping-pong x buffer,
//     register prefetch of next x tile, x stored as duplicated f32-pairs for
//     direct FFMA2 operands, loss via ||x||^2 + min-score identity.

#define Fh   32
#define Nh   4096
#define Dh   64
#define Kh   512
#define PADK 516                        // K + 4 floats: 16B-aligned rows
#define TILE_R 64
#define TILES_PER_F (Nh / TILE_R)       // 64
#define TOTAL_TILES (Fh * TILES_PER_F)  // 2048

// smem: sw[64][516] f32 | swn[512] f32 | sx2[2][64*64] u64 | sxn[2][64] f32
#define SX2_OFF   (Dh * PADK + Kh)                 // in floats (33536, 16B-mult)
#define SMEM_BYTES ((SX2_OFF + 2 * TILE_R * Dh * 2 + 2 * TILE_R) * 4)  // 200704

__device__ double g_loss;

__global__ void vq_init_kernel() { g_loss = 0.0; }

__device__ __forceinline__ unsigned long long ffma2(unsigned long long a,
                                                    unsigned long long b,
                                                    unsigned long long c) {
    unsigned long long d;
    asm("fma.rn.f32x2 %0, %1, %2, %3;" : "=l"(d) : "l"(a), "l"(b), "l"(c));
    return d;
}

__device__ __forceinline__ void unpack2(unsigned long long v, float& lo, float& hi) {
    unsigned int a, b;
    asm("mov.b64 {%0, %1}, %2;" : "=r"(a), "=r"(b) : "l"(v));
    lo = __uint_as_float(a);
    hi = __uint_as_float(b);
}

__global__ __launch_bounds__(256, 1)
void vq_main_kernel(const float* __restrict__ x,
                    const float* __restrict__ w,
                    float* __restrict__ out) {
    extern __shared__ float smem[];
    float* sw  = smem;                                  // [Dh][PADK]
    float* swn = sw + Dh * PADK;                        // [Kh]
    unsigned long long* sx2 =
        (unsigned long long*)(smem + SX2_OFF);          // [2][TILE_R*Dh] dup pairs
    float* sxn = (float*)(sx2 + 2 * TILE_R * Dh);       // [2][TILE_R] row ||x||^2

    const int tid  = threadIdx.x;
    const int wid  = tid >> 5;
    const int lane = tid & 31;

    const int G   = gridDim.x;
    const int per = TOTAL_TILES / G;
    const int rem = TOTAL_TILES % G;
    const int t0  = blockIdx.x * per + (blockIdx.x < rem ? blockIdx.x : rem);
    const int cnt = per + (blockIdx.x < rem ? 1 : 0);
    const int tend = t0 + cnt;

    double lsum = 0.0;
    int cur_f = -1;
    int buf = 0;

    // Initial prefetch of tile t0's x (64 rows x 64 d = 1024 float4, 4/thread)
    float4 pf[4];
    {
        const int f0 = t0 >> 6, tl0 = t0 & 63;
        const float4* xg =
            (const float4*)(x + ((size_t)f0 * Nh + (size_t)tl0 * TILE_R) * Dh);
        #pragma unroll
        for (int j = 0; j < 4; ++j) pf[j] = xg[tid + 256 * j];
    }

    for (int t = t0; t < tend; ++t) {
        const int f    = t >> 6;
        const int tile = t & 63;

        if (f != cur_f) {
            __syncthreads();  // prior readers of sw done
            const float4* wg = (const float4*)(w + (size_t)f * Dh * Kh);
            #pragma unroll 4
            for (int i = tid; i < Dh * (Kh / 4); i += 256) {
                const int d  = i >> 7;
                const int kq = i & 127;
                float4 v = wg[d * 128 + kq];
                *(float4*)&sw[d * PADK + kq * 4] = v;
            }
            __syncthreads();
            for (int k = tid; k < Kh; k += 256) {
                float s = 0.f;
                #pragma unroll
                for (int d = 0; d < Dh; ++d) {
                    const float v = sw[d * PADK + k];
                    s = fmaf(v, v, s);
                }
                swn[k] = s;
            }
            cur_f = f;
            __syncthreads();
        }

        // ---- Store prefetched x into sx2[buf] as dup pairs; row ||x||^2 ----
        {
            unsigned long long* dstb = sx2 + (size_t)buf * TILE_R * Dh;
            float s[4];
            #pragma unroll
            for (int j = 0; j < 4; ++j) {
                const int q   = tid + 256 * j;
                const int row = q >> 4;
                const int dq  = q & 15;
                const float4 a = pf[j];
                unsigned long long* dst = dstb + row * Dh + dq * 4;
                float4 p1 = make_float4(a.x, a.x, a.y, a.y);
                float4 p2 = make_float4(a.z, a.z, a.w, a.w);
                *(float4*)(dst)     = p1;
                *(float4*)(dst + 2) = p2;
                float t2 = fmaf(a.x, a.x, a.y * a.y);
                t2 = fmaf(a.z, a.z, t2);
                s[j] = fmaf(a.w, a.w, t2);
            }
            // half-warp reduce (threads sharing row are 16 consecutive lanes)
            #pragma unroll
            for (int off = 8; off > 0; off >>= 1)
                #pragma unroll
                for (int j = 0; j < 4; ++j)
                    s[j] += __shfl_xor_sync(0xffffffffu, s[j], off);
            if ((lane & 15) == 0) {
                const int rb = tid >> 4;
                #pragma unroll
                for (int j = 0; j < 4; ++j)
                    sxn[buf * TILE_R + rb + 16 * j] = s[j];
            }
        }
        __syncthreads();   // single barrier per tile

        // ---- Mainloop: 8 rows x 16 k per lane, packed f32x2 ----
        unsigned long long acc2[8][8];
        #pragma unroll
        for (int r = 0; r < 8; ++r)
            #pragma unroll
            for (int j = 0; j < 8; ++j) acc2[r][j] = 0ull;

        const float* swk = sw + lane * 4;
        const unsigned long long* xrow =
            sx2 + (size_t)buf * TILE_R * Dh + (wid * 8) * Dh;

        #pragma unroll 4
        for (int d = 0; d < Dh; ++d) {
            unsigned long long wp[8];
            #pragma unroll
            for (int c = 0; c < 4; ++c) {
                const ulonglong2 v =
                    *(const ulonglong2*)&swk[d * PADK + c * 128];
                wp[2 * c + 0] = v.x;
                wp[2 * c + 1] = v.y;
            }
            unsigned long long xp[8];
            #pragma unroll
            for (int r = 0; r < 8; ++r) xp[r] = xrow[r * Dh + d];  // broadcast
            #pragma unroll
            for (int r = 0; r < 8; ++r)
                #pragma unroll
                for (int j = 0; j < 8; ++j)
                    acc2[r][j] = ffma2(xp[r], wp[j], acc2[r][j]);
        }

        // ---- Scores + per-lane argmin (k ascending within lane) ----
        float wn[16];
        #pragma unroll
        for (int c = 0; c < 4; ++c) {
            const float4 v = *(const float4*)&swn[c * 128 + lane * 4];
            wn[c * 4 + 0] = v.x; wn[c * 4 + 1] = v.y;
            wn[c * 4 + 2] = v.z; wn[c * 4 + 3] = v.w;
        }

        float bval[8];
        int   bidx[8];
        #pragma unroll
        for (int r = 0; r < 8; ++r) { bval[r] = 3.4e38f; bidx[r] = 0; }

        #pragma unroll
        for (int c = 0; c < 4; ++c) {
            #pragma unroll
            for (int p = 0; p < 2; ++p) {
                const int jlo = c * 4 + p * 2;
                const int klo = c * 128 + lane * 4 + p * 2;
                #pragma unroll
                for (int r = 0; r < 8; ++r) {
                    float dlo, dhi;
                    unpack2(acc2[r][c * 2 + p], dlo, dhi);
                    const float slo = fmaf(-2.f, dlo, wn[jlo]);
                    const float shi = fmaf(-2.f, dhi, wn[jlo + 1]);
                    if (slo < bval[r]) { bval[r] = slo; bidx[r] = klo; }
                    if (shi < bval[r]) { bval[r] = shi; bidx[r] = klo + 1; }
                }
            }
        }

        // Prefetch next tile's x now (overlaps reduce/gather latency)
        if (t + 1 < tend) {
            const int f1 = (t + 1) >> 6, tl1 = (t + 1) & 63;
            const float4* xg =
                (const float4*)(x + ((size_t)f1 * Nh + (size_t)tl1 * TILE_R) * Dh);
            #pragma unroll
            for (int j = 0; j < 4; ++j) pf[j] = xg[tid + 256 * j];
        }

        // Warp-level argmin reduce (tie -> smaller k)
        #pragma unroll
        for (int off = 16; off > 0; off >>= 1) {
            #pragma unroll
            for (int r = 0; r < 8; ++r) {
                const float ov = __shfl_down_sync(0xffffffffu, bval[r], off);
                const int   oi = __shfl_down_sync(0xffffffffu, bidx[r], off);
                if (ov < bval[r] || (ov == bval[r] && oi < bidx[r])) {
                    bval[r] = ov; bidx[r] = oi;
                }
            }
        }
        // Loss on lane 0: dist = ||x||^2 + min score
        if (lane == 0) {
            #pragma unroll
            for (int r = 0; r < 8; ++r)
                lsum += (double)(bval[r] + sxn[buf * TILE_R + wid * 8 + r]);
        }
        #pragma unroll
        for (int r = 0; r < 8; ++r)
            bidx[r] = __shfl_sync(0xffffffffu, bidx[r], 0);

        // ---- Gather winning codewords, write output ----
        #pragma unroll
        for (int r = 0; r < 8; ++r) {
            const int kst = bidx[r];
            const int n = tile * TILE_R + wid * 8 + r;
            float* orow = out + ((size_t)f * Nh + n) * Dh;
            #pragma unroll
            for (int it = 0; it < 2; ++it) {
                const int d = it * 32 + lane;
                orow[d] = sw[d * PADK + kst];
            }
        }
        buf ^= 1;
    }

    if (lane == 0 && lsum != 0.0) atomicAdd(&g_loss, lsum);
    else if (lane == 0) atomicAdd(&g_loss, lsum);  // keep deterministic path
}

__global__ void vq_fin_kernel(float* __restrict__ out, int out_size) {
    const long long nelem = (long long)Fh * Nh * Dh;
    if (out_size > (int)nelem)
        out[nelem] = (float)(1.25 * g_loss / (double)nelem);
}

extern "C" void kernel_launch(void* const* d_in, const int* in_sizes, int n_in,
                              void* d_out, int out_size) {
    const float* x = (const float*)d_in[0];
    const float* w = (const float*)d_in[1];
    if (n_in >= 2 && in_sizes[0] == Fh * Dh * Kh && in_sizes[1] == Fh * Nh * Dh) {
        const float* tmp = x; x = w; w = tmp;
    }
    float* out = (float*)d_out;

    cudaFuncSetAttribute(vq_main_kernel,
                         cudaFuncAttributeMaxDynamicSharedMemorySize, SMEM_BYTES);

    int sms = 148;
    cudaDeviceGetAttribute(&sms, cudaDevAttrMultiProcessorCount, 0);
    if (sms <= 0) sms = 148;
    if (sms > TOTAL_TILES) sms = TOTAL_TILES;

    vq_init_kernel<<<1, 1>>>();
    vq_main_kernel<<<sms, 256, SMEM_BYTES>>>(x, w, out);
    vq_fin_kernel<<<1, 1>>>(out, out_size);
}

// round 7
// speedup vs baseline: 1.0050x; 1.0050x over previous
#include <cuda_runtime.h>
#include <cstdint>

// VectorQuantizer: F=32, N=4096, D=64, K=512
// out[f,n,:] = w[f,:,k*],  k* = argmin_k ||x - w_k||^2
// loss = 1.25 * mean((quantized - inputs)^2), appended at d_out[F*N*D]
//
// R5: TILE_R=64 (8 rows/lane), single barrier/tile via ping-pong x buffer,
//     register prefetch of next x tile, x stored as duplicated f32-pairs for
//     direct FFMA2 operands, loss via ||x||^2 + min-score identity.

#define Fh   32
#define Nh   4096
#define Dh   64
#define Kh   512
#define PADK 516                        // K + 4 floats: 16B-aligned rows
#define TILE_R 64
#define TILES_PER_F (Nh / TILE_R)       // 64
#define TOTAL_TILES (Fh * TILES_PER_F)  // 2048

// smem: sw[64][516] f32 | swn[512] f32 | sx2[2][64*64] u64 | sxn[2][64] f32
#define SX2_OFF   (Dh * PADK + Kh)                 // in floats (33536, 16B-mult)
#define SMEM_BYTES ((SX2_OFF + 2 * TILE_R * Dh * 2 + 2 * TILE_R) * 4)  // 200704

__device__ double g_loss;

__global__ void vq_init_kernel() { g_loss = 0.0; }

__device__ __forceinline__ unsigned long long ffma2(unsigned long long a,
                                                    unsigned long long b,
                                                    unsigned long long c) {
    unsigned long long d;
    asm("fma.rn.f32x2 %0, %1, %2, %3;" : "=l"(d) : "l"(a), "l"(b), "l"(c));
    return d;
}

__device__ __forceinline__ void unpack2(unsigned long long v, float& lo, float& hi) {
    unsigned int a, b;
    asm("mov.b64 {%0, %1}, %2;" : "=r"(a), "=r"(b) : "l"(v));
    lo = __uint_as_float(a);
    hi = __uint_as_float(b);
}

__global__ __launch_bounds__(256, 1)
void vq_main_kernel(const float* __restrict__ x,
                    const float* __restrict__ w,
                    float* __restrict__ out) {
    extern __shared__ float smem[];
    float* sw  = smem;                                  // [Dh][PADK]
    float* swn = sw + Dh * PADK;                        // [Kh]
    unsigned long long* sx2 =
        (unsigned long long*)(smem + SX2_OFF);          // [2][TILE_R*Dh] dup pairs
    float* sxn = (float*)(sx2 + 2 * TILE_R * Dh);       // [2][TILE_R] row ||x||^2

    const int tid  = threadIdx.x;
    const int wid  = tid >> 5;
    const int lane = tid & 31;

    const int G   = gridDim.x;
    const int per = TOTAL_TILES / G;
    const int rem = TOTAL_TILES % G;
    const int t0  = blockIdx.x * per + (blockIdx.x < rem ? blockIdx.x : rem);
    const int cnt = per + (blockIdx.x < rem ? 1 : 0);
    const int tend = t0 + cnt;

    double lsum = 0.0;
    int cur_f = -1;
    int buf = 0;

    // Initial prefetch of tile t0's x (64 rows x 64 d = 1024 float4, 4/thread)
    float4 pf[4];
    {
        const int f0 = t0 >> 6, tl0 = t0 & 63;
        const float4* xg =
            (const float4*)(x + ((size_t)f0 * Nh + (size_t)tl0 * TILE_R) * Dh);
        #pragma unroll
        for (int j = 0; j < 4; ++j) pf[j] = xg[tid + 256 * j];
    }

    for (int t = t0; t < tend; ++t) {
        const int f    = t >> 6;
        const int tile = t & 63;

        if (f != cur_f) {
            __syncthreads();  // prior readers of sw done
            const float4* wg = (const float4*)(w + (size_t)f * Dh * Kh);
            #pragma unroll 4
            for (int i = tid; i < Dh * (Kh / 4); i += 256) {
                const int d  = i >> 7;
                const int kq = i & 127;
                float4 v = wg[d * 128 + kq];
                *(float4*)&sw[d * PADK + kq * 4] = v;
            }
            __syncthreads();
            for (int k = tid; k < Kh; k += 256) {
                float s = 0.f;
                #pragma unroll
                for (int d = 0; d < Dh; ++d) {
                    const float v = sw[d * PADK + k];
                    s = fmaf(v, v, s);
                }
                swn[k] = s;
            }
            cur_f = f;
            __syncthreads();
        }

        // ---- Store prefetched x into sx2[buf] as dup pairs; row ||x||^2 ----
        {
            unsigned long long* dstb = sx2 + (size_t)buf * TILE_R * Dh;
            float s[4];
            #pragma unroll
            for (int j = 0; j < 4; ++j) {
                const int q   = tid + 256 * j;
                const int row = q >> 4;
                const int dq  = q & 15;
                const float4 a = pf[j];
                unsigned long long* dst = dstb + row * Dh + dq * 4;
                float4 p1 = make_float4(a.x, a.x, a.y, a.y);
                float4 p2 = make_float4(a.z, a.z, a.w, a.w);
                *(float4*)(dst)     = p1;
                *(float4*)(dst + 2) = p2;
                float t2 = fmaf(a.x, a.x, a.y * a.y);
                t2 = fmaf(a.z, a.z, t2);
                s[j] = fmaf(a.w, a.w, t2);
            }
            // half-warp reduce (threads sharing row are 16 consecutive lanes)
            #pragma unroll
            for (int off = 8; off > 0; off >>= 1)
                #pragma unroll
                for (int j = 0; j < 4; ++j)
                    s[j] += __shfl_xor_sync(0xffffffffu, s[j], off);
            if ((lane & 15) == 0) {
                const int rb = tid >> 4;
                #pragma unroll
                for (int j = 0; j < 4; ++j)
                    sxn[buf * TILE_R + rb + 16 * j] = s[j];
            }
        }
        __syncthreads();   // single barrier per tile

        // ---- Mainloop: 8 rows x 16 k per lane, packed f32x2 ----
        unsigned long long acc2[8][8];
        #pragma unroll
        for (int r = 0; r < 8; ++r)
            #pragma unroll
            for (int j = 0; j < 8; ++j) acc2[r][j] = 0ull;

        const float* swk = sw + lane * 4;
        const unsigned long long* xrow =
            sx2 + (size_t)buf * TILE_R * Dh + (wid * 8) * Dh;

        #pragma unroll 4
        for (int d = 0; d < Dh; ++d) {
            unsigned long long wp[8];
            #pragma unroll
            for (int c = 0; c < 4; ++c) {
                const ulonglong2 v =
                    *(const ulonglong2*)&swk[d * PADK + c * 128];
                wp[2 * c + 0] = v.x;
                wp[2 * c + 1] = v.y;
            }
            unsigned long long xp[8];
            #pragma unroll
            for (int r = 0; r < 8; ++r) xp[r] = xrow[r * Dh + d];  // broadcast
            #pragma unroll
            for (int r = 0; r < 8; ++r)
                #pragma unroll
                for (int j = 0; j < 8; ++j)
                    acc2[r][j] = ffma2(xp[r], wp[j], acc2[r][j]);
        }

        // ---- Scores + per-lane argmin (k ascending within lane) ----
        float wn[16];
        #pragma unroll
        for (int c = 0; c < 4; ++c) {
            const float4 v = *(const float4*)&swn[c * 128 + lane * 4];
            wn[c * 4 + 0] = v.x; wn[c * 4 + 1] = v.y;
            wn[c * 4 + 2] = v.z; wn[c * 4 + 3] = v.w;
        }

        float bval[8];
        int   bidx[8];
        #pragma unroll
        for (int r = 0; r < 8; ++r) { bval[r] = 3.4e38f; bidx[r] = 0; }

        #pragma unroll
        for (int c = 0; c < 4; ++c) {
            #pragma unroll
            for (int p = 0; p < 2; ++p) {
                const int jlo = c * 4 + p * 2;
                const int klo = c * 128 + lane * 4 + p * 2;
                #pragma unroll
                for (int r = 0; r < 8; ++r) {
                    float dlo, dhi;
                    unpack2(acc2[r][c * 2 + p], dlo, dhi);
                    const float slo = fmaf(-2.f, dlo, wn[jlo]);
                    const float shi = fmaf(-2.f, dhi, wn[jlo + 1]);
                    if (slo < bval[r]) { bval[r] = slo; bidx[r] = klo; }
                    if (shi < bval[r]) { bval[r] = shi; bidx[r] = klo + 1; }
                }
            }
        }

        // Prefetch next tile's x now (overlaps reduce/gather latency)
        if (t + 1 < tend) {
            const int f1 = (t + 1) >> 6, tl1 = (t + 1) & 63;
            const float4* xg =
                (const float4*)(x + ((size_t)f1 * Nh + (size_t)tl1 * TILE_R) * Dh);
            #pragma unroll
            for (int j = 0; j < 4; ++j) pf[j] = xg[tid + 256 * j];
        }

        // Warp-level argmin reduce (tie -> smaller k)
        #pragma unroll
        for (int off = 16; off > 0; off >>= 1) {
            #pragma unroll
            for (int r = 0; r < 8; ++r) {
                const float ov = __shfl_down_sync(0xffffffffu, bval[r], off);
                const int   oi = __shfl_down_sync(0xffffffffu, bidx[r], off);
                if (ov < bval[r] || (ov == bval[r] && oi < bidx[r])) {
                    bval[r] = ov; bidx[r] = oi;
                }
            }
        }
        // Loss on lane 0: dist = ||x||^2 + min score
        if (lane == 0) {
            #pragma unroll
            for (int r = 0; r < 8; ++r)
                lsum += (double)(bval[r] + sxn[buf * TILE_R + wid * 8 + r]);
        }
        #pragma unroll
        for (int r = 0; r < 8; ++r)
            bidx[r] = __shfl_sync(0xffffffffu, bidx[r], 0);

        // ---- Gather winning codewords, write output ----
        #pragma unroll
        for (int r = 0; r < 8; ++r) {
            const int kst = bidx[r];
            const int n = tile * TILE_R + wid * 8 + r;
            float* orow = out + ((size_t)f * Nh + n) * Dh;
            #pragma unroll
            for (int it = 0; it < 2; ++it) {
                const int d = it * 32 + lane;
                orow[d] = sw[d * PADK + kst];
            }
        }
        buf ^= 1;
    }

    if (lane == 0 && lsum != 0.0) atomicAdd(&g_loss, lsum);
    else if (lane == 0) atomicAdd(&g_loss, lsum);  // keep deterministic path
}

__global__ void vq_fin_kernel(float* __restrict__ out, int out_size) {
    const long long nelem = (long long)Fh * Nh * Dh;
    if (out_size > (int)nelem)
        out[nelem] = (float)(1.25 * g_loss / (double)nelem);
}

extern "C" void kernel_launch(void* const* d_in, const int* in_sizes, int n_in,
                              void* d_out, int out_size) {
    const float* x = (const float*)d_in[0];
    const float* w = (const float*)d_in[1];
    if (n_in >= 2 && in_sizes[0] == Fh * Dh * Kh && in_sizes[1] == Fh * Nh * Dh) {
        const float* tmp = x; x = w; w = tmp;
    }
    float* out = (float*)d_out;

    cudaFuncSetAttribute(vq_main_kernel,
                         cudaFuncAttributeMaxDynamicSharedMemorySize, SMEM_BYTES);

    int sms = 148;
    cudaDeviceGetAttribute(&sms, cudaDevAttrMultiProcessorCount, 0);
    if (sms <= 0) sms = 148;
    if (sms > TOTAL_TILES) sms = TOTAL_TILES;

    vq_init_kernel<<<1, 1>>>();
    vq_main_kernel<<<sms, 256, SMEM_BYTES>>>(x, w, out);
    vq_fin_kernel<<<1, 1>>>(out, out_size);
}